// round 1
// baseline (speedup 1.0000x reference)
#include <cuda_runtime.h>

namespace {
constexpr int B   = 4;
constexpr int P   = 3;
constexpr int C   = 32;
constexpr int HW  = 256;
constexpr int IMG = HW * HW;          // 65536 floats per channel image
constexpr int RES = 128;
constexpr int M   = RES * RES;        // 16384 points per batch (main)
constexpr int VS  = 64, VT = 32;
constexpr int MV  = VS * VS * VT;     // 131072 points per batch (video)

constexpr size_t OFF_VID  = (size_t)B * M * 3;              // 196608
constexpr size_t OFF_FEAT = OFF_VID + (size_t)B * 3 * MV;   // 1769472

struct Tap { int o0, o1, o2, o3; float w0, w1, w2, w3; };

// align_corners=False, zeros padding, H=W=256:
//   px = ((g+1)*256 - 1)*0.5 = g*128 + 127.5
__device__ __forceinline__ Tap make_tap(float gx, float gy) {
    Tap t;
    float x = fmaf(gx, 128.f, 127.5f);
    float y = fmaf(gy, 128.f, 127.5f);
    float xf = floorf(x), yf = floorf(y);
    int x0 = (int)xf, y0 = (int)yf;
    float fx = x - xf, fy = y - yf;
    int x1 = x0 + 1, y1 = y0 + 1;
    float vx0 = ((unsigned)x0 < 256u) ? 1.f : 0.f;
    float vx1 = ((unsigned)x1 < 256u) ? 1.f : 0.f;
    float vy0 = ((unsigned)y0 < 256u) ? 1.f : 0.f;
    float vy1 = ((unsigned)y1 < 256u) ? 1.f : 0.f;
    int cx0 = min(max(x0, 0), 255), cx1 = min(max(x1, 0), 255);
    int cy0 = min(max(y0, 0), 255), cy1 = min(max(y1, 0), 255);
    t.o0 = cy0 * 256 + cx0;  t.o1 = cy0 * 256 + cx1;
    t.o2 = cy1 * 256 + cx0;  t.o3 = cy1 * 256 + cx1;
    float wx0 = 1.f - fx, wx1 = fx, wy0 = 1.f - fy, wy1 = fy;
    t.w0 = wy0 * wx0 * vy0 * vx0;
    t.w1 = wy0 * wx1 * vy0 * vx1;
    t.w2 = wy1 * wx0 * vy1 * vx0;
    t.w3 = wy1 * wx1 * vy1 * vx1;
    return t;
}
} // namespace

// ---------------------------------------------------------------------------
// Main path: colors_coarse + features. One thread per point, full 35-col decode.
// ---------------------------------------------------------------------------
__global__ __launch_bounds__(256) void main_path_kernel(
    const float* __restrict__ planes, const float* __restrict__ c,
    const float* __restrict__ Wd, const float* __restrict__ bd,
    float* __restrict__ out)
{
    __shared__ float sW[96 * 36];   // rows padded to 36 -> float4-aligned
    __shared__ float sB[36];
    for (int t = threadIdx.x; t < 96 * 36; t += 256) {
        int k = t / 36, o = t - k * 36;
        sW[t] = (o < 35) ? Wd[k * 35 + o] : 0.f;
    }
    if (threadIdx.x < 36)
        sB[threadIdx.x] = (threadIdx.x < 35) ? bd[threadIdx.x] : 0.f;
    __syncthreads();

    int pi = blockIdx.x * 256 + threadIdx.x;   // < B*M
    int b = pi >> 14;
    int m = pi & (M - 1);
    int i = m >> 7, j = m & 127;

    const float* cb = c + b * 6;
    float c0 = cb[0], c1 = cb[1], c2 = cb[2];
    int axid = 0; float best = c0;
    if (c1 > best) { best = c1; axid = 1; }
    if (c2 > best) { axid = 2; }
    float tt = fmaf(cb[3], 2.f, -1.f);
    float gi = fmaf((float)i, 2.f / 127.f, -1.f);
    float gj = fmaf((float)j, 2.f / 127.f, -1.f);

    float X, Y, Z;
    if (axid == 0)      { X = tt; Y = gi; Z = gj; }
    else if (axid == 1) { X = gi; Y = tt; Z = gj; }
    else                { X = gi; Y = gj; Z = tt; }

    // plane0 samples (x,y); plane1 (x,z); plane2 (z,y)
    Tap t0 = make_tap(X, Y);
    Tap t1 = make_tap(X, Z);
    Tap t2 = make_tap(Z, Y);

    float acc[35];
#pragma unroll
    for (int o = 0; o < 35; o++) acc[o] = sB[o];

    const float* pb = planes + (size_t)b * P * C * IMG;
#pragma unroll
    for (int p = 0; p < 3; p++) {
        const Tap T = (p == 0) ? t0 : ((p == 1) ? t1 : t2);
        const float* bp = pb + (size_t)p * C * IMG;
#pragma unroll 2
        for (int ch = 0; ch < 32; ch++) {
            const float* img = bp + ch * IMG;
            float f = T.w0 * __ldg(img + T.o0) + T.w1 * __ldg(img + T.o1)
                    + T.w2 * __ldg(img + T.o2) + T.w3 * __ldg(img + T.o3);
            const float4* wr = reinterpret_cast<const float4*>(&sW[(p * 32 + ch) * 36]);
#pragma unroll
            for (int q = 0; q < 9; q++) {
                float4 w4 = wr[q];
                if (4 * q + 0 < 35) acc[4 * q + 0] = fmaf(f, w4.x, acc[4 * q + 0]);
                if (4 * q + 1 < 35) acc[4 * q + 1] = fmaf(f, w4.y, acc[4 * q + 1]);
                if (4 * q + 2 < 35) acc[4 * q + 2] = fmaf(f, w4.z, acc[4 * q + 2]);
                if (4 * q + 3 < 35) acc[4 * q + 3] = fmaf(f, w4.w, acc[4 * q + 3]);
            }
        }
    }

    size_t co = (size_t)pi * 3;
    out[co + 0] = acc[0]; out[co + 1] = acc[1]; out[co + 2] = acc[2];
    size_t fo = OFF_FEAT + (size_t)pi * 32;
#pragma unroll
    for (int o = 0; o < 32; o++) out[fo + o] = acc[3 + o];
}

// ---------------------------------------------------------------------------
// Video path: peep_vid rgb only. Lane-fastest axis = spatial i (the x coord),
// so plane2 (z,y) loads are warp-uniform (broadcast) and planes 0/1 walk W.
// ---------------------------------------------------------------------------
__global__ __launch_bounds__(256) void video_kernel(
    const float* __restrict__ planes, const float* __restrict__ c,
    const float* __restrict__ Wd, const float* __restrict__ bd,
    float* __restrict__ out)
{
    __shared__ float4 sW[96];   // first 3 decode columns per feature
    for (int t = threadIdx.x; t < 96; t += 256)
        sW[t] = make_float4(Wd[t * 35 + 0], Wd[t * 35 + 1], Wd[t * 35 + 2], 0.f);
    __syncthreads();

    int pi = blockIdx.x * 256 + threadIdx.x;   // = ((b*VT + k)*VS + j)*VS + i
    int i = pi & 63;
    int j = (pi >> 6) & 63;
    int k = (pi >> 12) & 31;
    int b = pi >> 17;

    const float* cb = c + b * 6;
    float X = fmaf(cb[4], 2.f, -1.f) + (float)i * (2.f / 63.f);
    float Y = fmaf(cb[5], 2.f, -1.f) + (float)j * (2.f / 63.f);
    float Z = fmaf((float)k, 2.f / 31.f, -1.f);

    Tap t0 = make_tap(X, Y);
    Tap t1 = make_tap(X, Z);
    Tap t2 = make_tap(Z, Y);

    float a0 = __ldg(bd + 0), a1 = __ldg(bd + 1), a2 = __ldg(bd + 2);

    const float* pb = planes + (size_t)b * P * C * IMG;
#pragma unroll
    for (int p = 0; p < 3; p++) {
        const Tap T = (p == 0) ? t0 : ((p == 1) ? t1 : t2);
        const float* bp = pb + (size_t)p * C * IMG;
#pragma unroll 4
        for (int ch = 0; ch < 32; ch++) {
            const float* img = bp + ch * IMG;
            float f = T.w0 * __ldg(img + T.o0) + T.w1 * __ldg(img + T.o1)
                    + T.w2 * __ldg(img + T.o2) + T.w3 * __ldg(img + T.o3);
            float4 w = sW[p * 32 + ch];
            a0 = fmaf(f, w.x, a0);
            a1 = fmaf(f, w.y, a1);
            a2 = fmaf(f, w.z, a2);
        }
    }

    // peep_vid[b, o, i, j, k]
    size_t base = OFF_VID + (size_t)b * 3 * MV + (size_t)i * (VS * VT) + (size_t)j * VT + k;
    out[base + 0 * MV] = a0;
    out[base + 1 * MV] = a1;
    out[base + 2 * MV] = a2;
}

extern "C" void kernel_launch(void* const* d_in, const int* in_sizes, int n_in,
                              void* d_out, int out_size) {
    const float* planes = (const float*)d_in[0];
    const float* c      = (const float*)d_in[1];
    const float* Wd     = (const float*)d_in[2];
    const float* bd     = (const float*)d_in[3];
    float* out = (float*)d_out;

    main_path_kernel<<<(B * M) / 256, 256>>>(planes, c, Wd, bd, out);
    video_kernel<<<(B * MV) / 256, 256>>>(planes, c, Wd, bd, out);
}

// round 2
// speedup vs baseline: 2.7153x; 2.7153x over previous
#include <cuda_runtime.h>

namespace {
constexpr int B   = 4;
constexpr int C   = 32;
constexpr int IMG = 256 * 256;
constexpr int RES = 128;
constexpr int M   = RES * RES;        // 16384 per batch
constexpr int VS  = 64, VT = 32;
constexpr int MV  = VS * VS * VT;     // 131072 per batch

constexpr size_t OFF_VID  = (size_t)B * M * 3;              // 196608
constexpr size_t OFF_FEAT = OFF_VID + (size_t)B * 3 * MV;   // 1769472

struct Tap { int o0, o1, o2, o3; float w0, w1, w2, w3; };

__device__ __forceinline__ Tap make_tap(float gx, float gy) {
    Tap t;
    float x = fmaf(gx, 128.f, 127.5f);
    float y = fmaf(gy, 128.f, 127.5f);
    float xf = floorf(x), yf = floorf(y);
    int x0 = (int)xf, y0 = (int)yf;
    float fx = x - xf, fy = y - yf;
    int x1 = x0 + 1, y1 = y0 + 1;
    float vx0 = ((unsigned)x0 < 256u) ? 1.f : 0.f;
    float vx1 = ((unsigned)x1 < 256u) ? 1.f : 0.f;
    float vy0 = ((unsigned)y0 < 256u) ? 1.f : 0.f;
    float vy1 = ((unsigned)y1 < 256u) ? 1.f : 0.f;
    int cx0 = min(max(x0, 0), 255), cx1 = min(max(x1, 0), 255);
    int cy0 = min(max(y0, 0), 255), cy1 = min(max(y1, 0), 255);
    t.o0 = cy0 * 256 + cx0;  t.o1 = cy0 * 256 + cx1;
    t.o2 = cy1 * 256 + cx0;  t.o3 = cy1 * 256 + cx1;
    float wx0 = 1.f - fx, wx1 = fx, wy0 = 1.f - fy, wy1 = fy;
    t.w0 = wy0 * wx0 * vy0 * vx0;
    t.w1 = wy0 * wx1 * vy0 * vx1;
    t.w2 = wy1 * wx0 * vy1 * vx0;
    t.w3 = wy1 * wx1 * vy1 * vx1;
    return t;
}

__device__ __forceinline__ int get_axid(const float* cb) {
    int axid = 0; float best = cb[0];
    if (cb[1] > best) { best = cb[1]; axid = 1; }
    if (cb[2] > best) axid = 2;
    return axid;
}
} // namespace

// Scratch (no allocations allowed)
__device__ float g_D[4 * 2 * 36 * 128];       // [b][axis(i=0,j=1)][o(35,pad36)][idx]
__device__ float g_A0[4 * 64 * 64 * 3];       // [b][j][i][rgb]  (main spatial plane of video)
__device__ float g_A1[4 * 64 * 32 * 3];       // [b][i][k][rgb]
__device__ float g_A2[4 * 64 * 32 * 3];       // [b][j][k][rgb]

// ---------------------------------------------------------------------------
// Kernel A: decoded 35-vec contributions of the two 1D planes (main path).
// 1024 threads total: (b, axis, idx).
// ---------------------------------------------------------------------------
__global__ __launch_bounds__(256) void precompute_1d_kernel(
    const float* __restrict__ planes, const float* __restrict__ c,
    const float* __restrict__ Wd)
{
    __shared__ float sW[96 * 36];
    for (int t = threadIdx.x; t < 96 * 36; t += 256) {
        int k = t / 36, o = t - k * 36;
        sW[t] = (o < 35) ? Wd[k * 35 + o] : 0.f;
    }
    __syncthreads();

    int tid = blockIdx.x * 256 + threadIdx.x;   // < 1024
    int b = tid >> 8;
    int axis = (tid >> 7) & 1;
    int idx = tid & 127;

    const float* cb = c + b * 6;
    int axid = get_axid(cb);
    float tt = fmaf(cb[3], 2.f, -1.f);
    float g = fmaf((float)idx, 2.f / 127.f, -1.f);

    int p; float gx, gy;
    if (axis == 0) {                       // 1D-in-i plane
        p = (axid == 2) ? 1 : 0;
        if (axid == 0) { gx = tt; gy = g; } else { gx = g; gy = tt; }
    } else {                               // 1D-in-j plane
        p = (axid == 0) ? 1 : 2;
        if (axid == 1) { gx = g; gy = tt; } else { gx = tt; gy = g; }
    }

    Tap T = make_tap(gx, gy);
    float acc[35];
#pragma unroll
    for (int o = 0; o < 35; o++) acc[o] = 0.f;

    const float* bp = planes + ((size_t)b * 3 + p) * C * IMG;
#pragma unroll 2
    for (int ch = 0; ch < 32; ch++) {
        const float* img = bp + ch * IMG;
        float f = T.w0 * __ldg(img + T.o0) + T.w1 * __ldg(img + T.o1)
                + T.w2 * __ldg(img + T.o2) + T.w3 * __ldg(img + T.o3);
        const float4* wr = reinterpret_cast<const float4*>(&sW[(p * 32 + ch) * 36]);
#pragma unroll
        for (int q = 0; q < 9; q++) {
            float4 w4 = wr[q];
            if (4 * q + 0 < 35) acc[4 * q + 0] = fmaf(f, w4.x, acc[4 * q + 0]);
            if (4 * q + 1 < 35) acc[4 * q + 1] = fmaf(f, w4.y, acc[4 * q + 1]);
            if (4 * q + 2 < 35) acc[4 * q + 2] = fmaf(f, w4.z, acc[4 * q + 2]);
            if (4 * q + 3 < 35) acc[4 * q + 3] = fmaf(f, w4.w, acc[4 * q + 3]);
        }
    }

    float* dst = g_D + ((size_t)(b * 2 + axis) * 36) * 128 + idx;
#pragma unroll
    for (int o = 0; o < 35; o++) dst[o * 128] = acc[o];
}

// ---------------------------------------------------------------------------
// Kernel B: main path. Gather only the 2D plane; add precomputed 1D parts.
// Per-batch lane-fastest axis matches the plane's gx (W) axis.
// ---------------------------------------------------------------------------
__global__ __launch_bounds__(256) void main_path_kernel(
    const float* __restrict__ planes, const float* __restrict__ c,
    const float* __restrict__ Wd, const float* __restrict__ bd,
    float* __restrict__ out)
{
    __shared__ float sW[96 * 36];
    __shared__ float sB[36];
    __shared__ float sF[256 * 33];
    for (int t = threadIdx.x; t < 96 * 36; t += 256) {
        int k = t / 36, o = t - k * 36;
        sW[t] = (o < 35) ? Wd[k * 35 + o] : 0.f;
    }
    if (threadIdx.x < 36)
        sB[threadIdx.x] = (threadIdx.x < 35) ? bd[threadIdx.x] : 0.f;
    __syncthreads();

    int pi = blockIdx.x * 256 + threadIdx.x;
    int b = pi >> 14;
    int t = pi & (M - 1);

    const float* cb = c + b * 6;
    int axid = get_axid(cb);

    int i, j;
    if (axid == 0) { i = t >> 7; j = t & 127; }
    else           { i = t & 127; j = t >> 7; }
    float gi = fmaf((float)i, 2.f / 127.f, -1.f);
    float gj = fmaf((float)j, 2.f / 127.f, -1.f);

    int p2; float gx, gy;
    if (axid == 0)      { p2 = 2; gx = gj; gy = gi; }
    else if (axid == 1) { p2 = 1; gx = gi; gy = gj; }
    else                { p2 = 0; gx = gi; gy = gj; }

    Tap T = make_tap(gx, gy);

    const float* Di = g_D + (size_t)(b * 2 + 0) * 36 * 128 + i;
    const float* Dj = g_D + (size_t)(b * 2 + 1) * 36 * 128 + j;
    float acc[35];
#pragma unroll
    for (int o = 0; o < 35; o++)
        acc[o] = sB[o] + __ldg(Di + o * 128) + __ldg(Dj + o * 128);

    const float* bp = planes + ((size_t)b * 3 + p2) * C * IMG;
#pragma unroll 2
    for (int ch = 0; ch < 32; ch++) {
        const float* img = bp + ch * IMG;
        float f = T.w0 * __ldg(img + T.o0) + T.w1 * __ldg(img + T.o1)
                + T.w2 * __ldg(img + T.o2) + T.w3 * __ldg(img + T.o3);
        const float4* wr = reinterpret_cast<const float4*>(&sW[(p2 * 32 + ch) * 36]);
#pragma unroll
        for (int q = 0; q < 9; q++) {
            float4 w4 = wr[q];
            if (4 * q + 0 < 35) acc[4 * q + 0] = fmaf(f, w4.x, acc[4 * q + 0]);
            if (4 * q + 1 < 35) acc[4 * q + 1] = fmaf(f, w4.y, acc[4 * q + 1]);
            if (4 * q + 2 < 35) acc[4 * q + 2] = fmaf(f, w4.z, acc[4 * q + 2]);
            if (4 * q + 3 < 35) acc[4 * q + 3] = fmaf(f, w4.w, acc[4 * q + 3]);
        }
    }

    int m_out = (axid == 0) ? t : (i * 128 + j);
    size_t co = ((size_t)b * M + m_out) * 3;
    out[co + 0] = acc[0]; out[co + 1] = acc[1]; out[co + 2] = acc[2];

    // stage features, then write warp-coalesced (one warp = one point's 32 feats)
#pragma unroll
    for (int o = 0; o < 32; o++) sF[threadIdx.x * 33 + o] = acc[3 + o];
    __syncthreads();

    int lane = threadIdx.x & 31;
    int wid = threadIdx.x >> 5;
    int t_base = (blockIdx.x & 63) * 256;
    for (int p = wid; p < 256; p += 8) {
        int tq = t_base + p;
        int ii, jj, mo;
        if (axid == 0) { mo = tq; }
        else { ii = tq & 127; jj = tq >> 7; mo = ii * 128 + jj; }
        out[OFF_FEAT + ((size_t)b * M + mo) * 32 + lane] = sF[p * 33 + lane];
    }
}

// ---------------------------------------------------------------------------
// Kernel C: video per-plane decoded RGB contributions (8192 points/batch).
// ---------------------------------------------------------------------------
__global__ __launch_bounds__(256) void video_planes_kernel(
    const float* __restrict__ planes, const float* __restrict__ c,
    const float* __restrict__ Wd)
{
    __shared__ float4 sW3[96];
    for (int t = threadIdx.x; t < 96; t += 256)
        sW3[t] = make_float4(Wd[t * 35 + 0], Wd[t * 35 + 1], Wd[t * 35 + 2], 0.f);
    __syncthreads();

    int tid = blockIdx.x * 256 + threadIdx.x;  // < 4*8192
    int b = tid >> 13;
    int r = tid & 8191;

    const float* cb = c + b * 6;
    float x0 = fmaf(cb[4], 2.f, -1.f);
    float y0 = fmaf(cb[5], 2.f, -1.f);

    int p; float gx, gy; float* dst;
    if (r < 4096) {                     // plane0: (X(i), Y(j))
        int i = r & 63, j = r >> 6;
        p = 0;
        gx = x0 + (float)i * (2.f / 63.f);
        gy = y0 + (float)j * (2.f / 63.f);
        dst = g_A0 + ((size_t)(b * 64 + j) * 64 + i) * 3;
    } else if (r < 6144) {              // plane1: (X(i), Z(k)) -> [b][i][k]
        int rr = r - 4096;
        int i = rr & 63, k = rr >> 6;
        p = 1;
        gx = x0 + (float)i * (2.f / 63.f);
        gy = fmaf((float)k, 2.f / 31.f, -1.f);
        dst = g_A1 + ((size_t)(b * 64 + i) * 32 + k) * 3;
    } else {                            // plane2: (Z(k), Y(j)) -> [b][j][k]
        int rr = r - 6144;
        int k = rr & 31, j = rr >> 5;
        p = 2;
        gx = fmaf((float)k, 2.f / 31.f, -1.f);
        gy = y0 + (float)j * (2.f / 63.f);
        dst = g_A2 + ((size_t)(b * 64 + j) * 32 + k) * 3;
    }

    Tap T = make_tap(gx, gy);
    float a0 = 0.f, a1 = 0.f, a2 = 0.f;
    const float* bp = planes + ((size_t)b * 3 + p) * C * IMG;
#pragma unroll 4
    for (int ch = 0; ch < 32; ch++) {
        const float* img = bp + ch * IMG;
        float f = T.w0 * __ldg(img + T.o0) + T.w1 * __ldg(img + T.o1)
                + T.w2 * __ldg(img + T.o2) + T.w3 * __ldg(img + T.o3);
        float4 w = sW3[p * 32 + ch];
        a0 = fmaf(f, w.x, a0);
        a1 = fmaf(f, w.y, a1);
        a2 = fmaf(f, w.z, a2);
    }
    dst[0] = a0; dst[1] = a1; dst[2] = a2;
}

// ---------------------------------------------------------------------------
// Kernel D: video assembly. out = bias + A0[i,j] + A1[i,k] + A2[j,k].
// k lane-fastest: A0 broadcast, A1/A2 contiguous, writes coalesced.
// ---------------------------------------------------------------------------
__global__ __launch_bounds__(256) void video_assemble_kernel(
    const float* __restrict__ bd, float* __restrict__ out)
{
    int pi = blockIdx.x * 256 + threadIdx.x;   // ((b*64+i)*64+j)*32+k
    int k = pi & 31;
    int j = (pi >> 5) & 63;
    int i = (pi >> 11) & 63;
    int b = pi >> 17;

    const float* a0 = g_A0 + ((size_t)(b * 64 + j) * 64 + i) * 3;   // uniform in warp
    const float* a1 = g_A1 + ((size_t)(b * 64 + i) * 32 + k) * 3;
    const float* a2 = g_A2 + ((size_t)(b * 64 + j) * 32 + k) * 3;

    float v0 = __ldg(bd + 0) + a0[0] + a1[0] + a2[0];
    float v1 = __ldg(bd + 1) + a0[1] + a1[1] + a2[1];
    float v2 = __ldg(bd + 2) + a0[2] + a1[2] + a2[2];

    size_t base = OFF_VID + (size_t)b * 3 * MV + (size_t)i * (VS * VT) + (size_t)j * VT + k;
    out[base + 0 * MV] = v0;
    out[base + 1 * MV] = v1;
    out[base + 2 * MV] = v2;
}

extern "C" void kernel_launch(void* const* d_in, const int* in_sizes, int n_in,
                              void* d_out, int out_size) {
    const float* planes = (const float*)d_in[0];
    const float* c      = (const float*)d_in[1];
    const float* Wd     = (const float*)d_in[2];
    const float* bd     = (const float*)d_in[3];
    float* out = (float*)d_out;

    precompute_1d_kernel<<<4, 256>>>(planes, c, Wd);
    video_planes_kernel<<<128, 256>>>(planes, c, Wd);
    main_path_kernel<<<256, 256>>>(planes, c, Wd, bd, out);
    video_assemble_kernel<<<2048, 256>>>(bd, out);
}

// round 3
// speedup vs baseline: 4.9263x; 1.8143x over previous
#include <cuda_runtime.h>

namespace {
constexpr int B   = 4;
constexpr int C   = 32;
constexpr int IMG = 256 * 256;
constexpr int RES = 128;
constexpr int M   = RES * RES;        // 16384 per batch
constexpr int VS  = 64, VT = 32;
constexpr int MV  = VS * VS * VT;     // 131072 per batch

constexpr size_t OFF_VID  = (size_t)B * M * 3;              // 196608
constexpr size_t OFF_FEAT = OFF_VID + (size_t)B * 3 * MV;   // 1769472

constexpr int K1_VID_BLOCKS = 128;    // video_planes part of kernel1
constexpr int K1_PRE_BLOCKS = 8;      // precompute part (b,axis)
constexpr int K2_MAIN_BLOCKS = 256;   // main path part of kernel2
constexpr int K2_ASM_BLOCKS  = 512;   // assemble part of kernel2

struct Tap { int o0, o1, o2, o3; float w0, w1, w2, w3; };

__device__ __forceinline__ Tap make_tap(float gx, float gy) {
    Tap t;
    float x = fmaf(gx, 128.f, 127.5f);
    float y = fmaf(gy, 128.f, 127.5f);
    float xf = floorf(x), yf = floorf(y);
    int x0 = (int)xf, y0 = (int)yf;
    float fx = x - xf, fy = y - yf;
    int x1 = x0 + 1, y1 = y0 + 1;
    float vx0 = ((unsigned)x0 < 256u) ? 1.f : 0.f;
    float vx1 = ((unsigned)x1 < 256u) ? 1.f : 0.f;
    float vy0 = ((unsigned)y0 < 256u) ? 1.f : 0.f;
    float vy1 = ((unsigned)y1 < 256u) ? 1.f : 0.f;
    int cx0 = min(max(x0, 0), 255), cx1 = min(max(x1, 0), 255);
    int cy0 = min(max(y0, 0), 255), cy1 = min(max(y1, 0), 255);
    t.o0 = cy0 * 256 + cx0;  t.o1 = cy0 * 256 + cx1;
    t.o2 = cy1 * 256 + cx0;  t.o3 = cy1 * 256 + cx1;
    float wx0 = 1.f - fx, wx1 = fx, wy0 = 1.f - fy, wy1 = fy;
    t.w0 = wy0 * wx0 * vy0 * vx0;
    t.w1 = wy0 * wx1 * vy0 * vx1;
    t.w2 = wy1 * wx0 * vy1 * vx0;
    t.w3 = wy1 * wx1 * vy1 * vx1;
    return t;
}

__device__ __forceinline__ int get_axid(const float* cb) {
    int axid = 0; float best = cb[0];
    if (cb[1] > best) { best = cb[1]; axid = 1; }
    if (cb[2] > best) axid = 2;
    return axid;
}
} // namespace

// Scratch (no allocations allowed)
__device__ float g_D[4 * 2 * 36 * 128];        // [b][axis][o(pad36)][idx]
__device__ float g_A0[3 * 4 * 64 * 64];        // [rgb][b][j][i]
__device__ float g_A1[3 * 4 * 64 * 32];        // [rgb][b][i][k]
__device__ float g_A2[3 * 4 * 64 * 32];        // [rgb][b][j][k]

// ---------------------------------------------------------------------------
// Kernel 1: blocks [0,128) = video per-plane RGB tables,
//           blocks [128,136) = 1D-plane 35-vec precompute (one block per b,axis)
// ---------------------------------------------------------------------------
__global__ __launch_bounds__(256) void prep_kernel(
    const float* __restrict__ planes, const float* __restrict__ c,
    const float* __restrict__ Wd)
{
    if (blockIdx.x < K1_VID_BLOCKS) {
        // ---- video planes part ----
        __shared__ float4 sW3[96];
        for (int t = threadIdx.x; t < 96; t += 256)
            sW3[t] = make_float4(Wd[t * 35 + 0], Wd[t * 35 + 1], Wd[t * 35 + 2], 0.f);
        __syncthreads();

        int tid = blockIdx.x * 256 + threadIdx.x;  // < 4*8192
        int b = tid >> 13;
        int r = tid & 8191;

        const float* cb = c + b * 6;
        float x0 = fmaf(cb[4], 2.f, -1.f);
        float y0 = fmaf(cb[5], 2.f, -1.f);

        int p; float gx, gy; int didx; float* dbase; int dstride;
        if (r < 4096) {                     // plane0: (X(i), Y(j)) -> [b][j][i]
            int i = r & 63, j = r >> 6;
            p = 0;
            gx = x0 + (float)i * (2.f / 63.f);
            gy = y0 + (float)j * (2.f / 63.f);
            dbase = g_A0; dstride = 4 * 64 * 64;
            didx = (b * 64 + j) * 64 + i;
        } else if (r < 6144) {              // plane1: (X(i), Z(k)) -> [b][i][k]
            int rr = r - 4096;
            int i = rr & 63, k = rr >> 6;
            p = 1;
            gx = x0 + (float)i * (2.f / 63.f);
            gy = fmaf((float)k, 2.f / 31.f, -1.f);
            dbase = g_A1; dstride = 4 * 64 * 32;
            didx = (b * 64 + i) * 32 + k;
        } else {                            // plane2: (Z(k), Y(j)) -> [b][j][k]
            int rr = r - 6144;
            int k = rr & 31, j = rr >> 5;
            p = 2;
            gx = fmaf((float)k, 2.f / 31.f, -1.f);
            gy = y0 + (float)j * (2.f / 63.f);
            dbase = g_A2; dstride = 4 * 64 * 32;
            didx = (b * 64 + j) * 32 + k;
        }

        Tap T = make_tap(gx, gy);
        float a0 = 0.f, a1 = 0.f, a2 = 0.f;
        const float* bp = planes + ((size_t)b * 3 + p) * C * IMG;
        for (int cbase = 0; cbase < 32; cbase += 8) {
            float v0[8], v1[8], v2[8], v3[8];
#pragma unroll
            for (int cc = 0; cc < 8; cc++) {
                const float* img = bp + (cbase + cc) * IMG;
                v0[cc] = __ldg(img + T.o0); v1[cc] = __ldg(img + T.o1);
                v2[cc] = __ldg(img + T.o2); v3[cc] = __ldg(img + T.o3);
            }
#pragma unroll
            for (int cc = 0; cc < 8; cc++) {
                float f = T.w0 * v0[cc] + T.w1 * v1[cc] + T.w2 * v2[cc] + T.w3 * v3[cc];
                float4 w = sW3[p * 32 + cbase + cc];
                a0 = fmaf(f, w.x, a0);
                a1 = fmaf(f, w.y, a1);
                a2 = fmaf(f, w.z, a2);
            }
        }
        dbase[0 * dstride + didx] = a0;
        dbase[1 * dstride + didx] = a1;
        dbase[2 * dstride + didx] = a2;
    } else {
        // ---- 1D precompute part: block = (b, axis); thread = (half, idx) ----
        __shared__ float sWp[32 * 36];
        __shared__ float sP[128 * 37];

        int gid = blockIdx.x - K1_VID_BLOCKS;   // 0..7
        int b = gid >> 1;
        int axis = gid & 1;

        const float* cb = c + b * 6;
        int axid = get_axid(cb);
        float tt = fmaf(cb[3], 2.f, -1.f);

        int p;
        bool g_is_x;     // whether the varying coord is gx
        if (axis == 0) { p = (axid == 2) ? 1 : 0; g_is_x = (axid != 0); }
        else           { p = (axid == 0) ? 1 : 2; g_is_x = (axid == 1); }

        for (int t = threadIdx.x; t < 32 * 36; t += 256) {
            int k = t / 36, o = t - k * 36;
            sWp[t] = (o < 35) ? Wd[(p * 32 + k) * 35 + o] : 0.f;
        }
        __syncthreads();

        int idx = threadIdx.x & 127;
        int half = threadIdx.x >> 7;            // 0/1 -> channels [0,16)/[16,32)

        float g = fmaf((float)idx, 2.f / 127.f, -1.f);
        float gx = g_is_x ? g : tt;
        float gy = g_is_x ? tt : g;
        Tap T = make_tap(gx, gy);

        float acc[35];
#pragma unroll
        for (int o = 0; o < 35; o++) acc[o] = 0.f;

        const float* bp = planes + ((size_t)b * 3 + p) * C * IMG;
        for (int cbase = half * 16; cbase < half * 16 + 16; cbase += 8) {
            float v0[8], v1[8], v2[8], v3[8];
#pragma unroll
            for (int cc = 0; cc < 8; cc++) {
                const float* img = bp + (cbase + cc) * IMG;
                v0[cc] = __ldg(img + T.o0); v1[cc] = __ldg(img + T.o1);
                v2[cc] = __ldg(img + T.o2); v3[cc] = __ldg(img + T.o3);
            }
#pragma unroll
            for (int cc = 0; cc < 8; cc++) {
                float f = T.w0 * v0[cc] + T.w1 * v1[cc] + T.w2 * v2[cc] + T.w3 * v3[cc];
                const float4* wr = reinterpret_cast<const float4*>(&sWp[(cbase + cc) * 36]);
#pragma unroll
                for (int q = 0; q < 9; q++) {
                    float4 w4 = wr[q];
                    if (4 * q + 0 < 35) acc[4 * q + 0] = fmaf(f, w4.x, acc[4 * q + 0]);
                    if (4 * q + 1 < 35) acc[4 * q + 1] = fmaf(f, w4.y, acc[4 * q + 1]);
                    if (4 * q + 2 < 35) acc[4 * q + 2] = fmaf(f, w4.z, acc[4 * q + 2]);
                    if (4 * q + 3 < 35) acc[4 * q + 3] = fmaf(f, w4.w, acc[4 * q + 3]);
                }
            }
        }

        if (half == 1) {
#pragma unroll
            for (int o = 0; o < 35; o++) sP[idx * 37 + o] = acc[o];
        }
        __syncthreads();
        if (half == 0) {
            float* dst = g_D + (size_t)(b * 2 + axis) * 36 * 128 + idx;
#pragma unroll
            for (int o = 0; o < 35; o++) dst[o * 128] = acc[o] + sP[idx * 37 + o];
        }
    }
}

// ---------------------------------------------------------------------------
// Kernel 2: blocks [0,256) = main path; blocks [256,768) = video assembly.
// ---------------------------------------------------------------------------
__global__ __launch_bounds__(256) void render_kernel(
    const float* __restrict__ planes, const float* __restrict__ c,
    const float* __restrict__ Wd, const float* __restrict__ bd,
    float* __restrict__ out)
{
    if (blockIdx.x < K2_MAIN_BLOCKS) {
        __shared__ float sWp[32 * 36];
        __shared__ float sB[36];
        __shared__ float sF[256 * 33];

        int pi = blockIdx.x * 256 + threadIdx.x;
        int b = pi >> 14;
        int t = pi & (M - 1);

        const float* cb = c + b * 6;
        int axid = get_axid(cb);
        int p2 = (axid == 0) ? 2 : ((axid == 1) ? 1 : 0);

        for (int tt = threadIdx.x; tt < 32 * 36; tt += 256) {
            int k = tt / 36, o = tt - k * 36;
            sWp[tt] = (o < 35) ? Wd[(p2 * 32 + k) * 35 + o] : 0.f;
        }
        if (threadIdx.x < 36)
            sB[threadIdx.x] = (threadIdx.x < 35) ? bd[threadIdx.x] : 0.f;
        __syncthreads();

        int i, j;
        if (axid == 0) { i = t >> 7; j = t & 127; }
        else           { i = t & 127; j = t >> 7; }
        float gi = fmaf((float)i, 2.f / 127.f, -1.f);
        float gj = fmaf((float)j, 2.f / 127.f, -1.f);

        float gx, gy;
        if (axid == 0)      { gx = gj; gy = gi; }
        else                { gx = gi; gy = gj; }

        Tap T = make_tap(gx, gy);

        const float* Di = g_D + (size_t)(b * 2 + 0) * 36 * 128 + i;
        const float* Dj = g_D + (size_t)(b * 2 + 1) * 36 * 128 + j;
        float acc[35];
#pragma unroll
        for (int o = 0; o < 35; o++)
            acc[o] = sB[o] + __ldg(Di + o * 128) + __ldg(Dj + o * 128);

        const float* bp = planes + ((size_t)b * 3 + p2) * C * IMG;
        for (int cbase = 0; cbase < 32; cbase += 8) {
            float v0[8], v1[8], v2[8], v3[8];
#pragma unroll
            for (int cc = 0; cc < 8; cc++) {
                const float* img = bp + (cbase + cc) * IMG;
                v0[cc] = __ldg(img + T.o0); v1[cc] = __ldg(img + T.o1);
                v2[cc] = __ldg(img + T.o2); v3[cc] = __ldg(img + T.o3);
            }
#pragma unroll
            for (int cc = 0; cc < 8; cc++) {
                float f = T.w0 * v0[cc] + T.w1 * v1[cc] + T.w2 * v2[cc] + T.w3 * v3[cc];
                const float4* wr = reinterpret_cast<const float4*>(&sWp[(cbase + cc) * 36]);
#pragma unroll
                for (int q = 0; q < 9; q++) {
                    float4 w4 = wr[q];
                    if (4 * q + 0 < 35) acc[4 * q + 0] = fmaf(f, w4.x, acc[4 * q + 0]);
                    if (4 * q + 1 < 35) acc[4 * q + 1] = fmaf(f, w4.y, acc[4 * q + 1]);
                    if (4 * q + 2 < 35) acc[4 * q + 2] = fmaf(f, w4.z, acc[4 * q + 2]);
                    if (4 * q + 3 < 35) acc[4 * q + 3] = fmaf(f, w4.w, acc[4 * q + 3]);
                }
            }
        }

        int m_out = (axid == 0) ? t : (i * 128 + j);
        size_t co = ((size_t)b * M + m_out) * 3;
        out[co + 0] = acc[0]; out[co + 1] = acc[1]; out[co + 2] = acc[2];

#pragma unroll
        for (int o = 0; o < 32; o++) sF[threadIdx.x * 33 + o] = acc[3 + o];
        __syncthreads();

        int lane = threadIdx.x & 31;
        int wid = threadIdx.x >> 5;
        int t_base = (blockIdx.x & 63) * 256;
        for (int pp = wid; pp < 256; pp += 8) {
            int tq = t_base + pp;
            int mo;
            if (axid == 0) { mo = tq; }
            else { mo = (tq & 127) * 128 + (tq >> 7); }
            out[OFF_FEAT + ((size_t)b * M + mo) * 32 + lane] = sF[pp * 33 + lane];
        }
    } else {
        // ---- assembly: thread handles 4 consecutive k ----
        int tid = (blockIdx.x - K2_MAIN_BLOCKS) * 256 + threadIdx.x;
        int k4 = (tid & 7) << 2;
        int j = (tid >> 3) & 63;
        int i = (tid >> 9) & 63;
        int b = tid >> 15;

        size_t base = OFF_VID + (size_t)b * 3 * MV + (size_t)i * (VS * VT) + (size_t)j * VT + k4;
#pragma unroll
        for (int rgb = 0; rgb < 3; rgb++) {
            float a0 = g_A0[(size_t)(rgb * 4 + b) * 4096 + j * 64 + i];
            const float4 a1 = *reinterpret_cast<const float4*>(
                &g_A1[(size_t)(rgb * 4 + b) * 2048 + i * 32 + k4]);
            const float4 a2 = *reinterpret_cast<const float4*>(
                &g_A2[(size_t)(rgb * 4 + b) * 2048 + j * 32 + k4]);
            float bias = __ldg(bd + rgb);
            float4 v;
            v.x = bias + a0 + a1.x + a2.x;
            v.y = bias + a0 + a1.y + a2.y;
            v.z = bias + a0 + a1.z + a2.z;
            v.w = bias + a0 + a1.w + a2.w;
            *reinterpret_cast<float4*>(&out[base + (size_t)rgb * MV]) = v;
        }
    }
}

extern "C" void kernel_launch(void* const* d_in, const int* in_sizes, int n_in,
                              void* d_out, int out_size) {
    const float* planes = (const float*)d_in[0];
    const float* c      = (const float*)d_in[1];
    const float* Wd     = (const float*)d_in[2];
    const float* bd     = (const float*)d_in[3];
    float* out = (float*)d_out;

    prep_kernel<<<K1_VID_BLOCKS + K1_PRE_BLOCKS, 256>>>(planes, c, Wd);
    render_kernel<<<K2_MAIN_BLOCKS + K2_ASM_BLOCKS, 256>>>(planes, c, Wd, bd, out);
}